// round 14
// baseline (speedup 1.0000x reference)
#include <cuda_runtime.h>
#include <cuda_bf16.h>
#include <cstddef>
#include <math.h>

// Problem dims
static constexpr int B_  = 32;
static constexpr int T_  = 1024;
static constexpr int H_  = 512;
static constexpr int G4  = 2048;   // 4*H gate columns per layer
static constexpr int NCTA = 128;   // persistent CTAs, each owns 4 hidden cols
static constexpr int THR  = 512;   // threads per recurrent CTA

static constexpr int AS_STRIDE = 68;   // precompute tiles
static constexpr int Z_STRIDE  = 36;   // z rows: 16B-aligned, 36%32=4

// Recurrent SMEM layout (floats):
//   w01 [512][8][4]  (slices 0+1 interleaved)   [0, 16384)
//   w2  [512][8][2]                              [16384, 24576)
//   bufA (h0 tile -> zI)                         [24576, 40960)
//   bufB (h1 tile -> zS)                         [40960, 57344)
//   mbars (8 x 8B)                               [57344, 57360)
//   h0r  [2][128] residual stash                 [57360, 57616)
static constexpr int W01_OFF  = 0;
static constexpr int W2_OFF   = 16384;
static constexpr int BUFA_OFF = 24576;
static constexpr int BUFB_OFF = 40960;
static constexpr int MBAR_OFF = 57344;
static constexpr int H0R_OFF  = 57360;
static constexpr int SMEM_FLOATS = 57616;
static constexpr int SMEM_BYTES  = SMEM_FLOATS * 4;   // 230464

// -------- device-global scratch (allocations forbidden) --------
__device__ __align__(128) float g_Z0p[(size_t)T_ * G4 * B_];   // [t][gate_col][b]
__device__ __align__(128) float g_h[2][2][H_][B_];             // [layer][parity][col][b]
__device__ unsigned g_ctr[2][4];                               // cumulative chunk counters

__device__ __forceinline__ float fsigm(float z) { return 1.0f / (1.0f + __expf(-z)); }
__device__ __forceinline__ float ftanh(float z) { return 2.0f / (1.0f + __expf(-2.0f * z)) - 1.0f; }

__device__ __forceinline__ unsigned long long dup2(float v) {
    unsigned long long r;
    asm("mov.b64 %0, {%1, %1};" : "=l"(r) : "f"(v));
    return r;
}
__device__ __forceinline__ void fma2(unsigned long long& acc,
                                     unsigned long long a, unsigned long long b) {
    asm("fma.rn.f32x2 %0, %1, %2, %0;" : "+l"(acc) : "l"(a), "l"(b));
}
__device__ __forceinline__ unsigned ld_acq(const unsigned* p) {
    unsigned v;
    asm volatile("ld.global.acquire.gpu.u32 %0, [%1];" : "=r"(v) : "l"(p) : "memory");
    return v;
}

// -------- mbarrier / bulk-copy helpers --------
__device__ __forceinline__ unsigned smem_u32(const void* p) {
    return (unsigned)__cvta_generic_to_shared(p);
}
__device__ __forceinline__ void mbar_init(unsigned mbar, unsigned cnt) {
    asm volatile("mbarrier.init.shared.b64 [%0], %1;" :: "r"(mbar), "r"(cnt) : "memory");
}
__device__ __forceinline__ void mbar_expect_tx(unsigned mbar, unsigned bytes) {
    asm volatile("mbarrier.arrive.expect_tx.shared.b64 _, [%0], %1;"
                 :: "r"(mbar), "r"(bytes) : "memory");
}
__device__ __forceinline__ void bulk_g2s(unsigned dst, const void* src, unsigned bytes,
                                         unsigned mbar) {
    asm volatile("cp.async.bulk.shared::cta.global.mbarrier::complete_tx::bytes "
                 "[%0], [%1], %2, [%3];"
                 :: "r"(dst), "l"(src), "r"(bytes), "r"(mbar) : "memory");
}
__device__ __forceinline__ void mbar_wait(unsigned mbar, unsigned parity) {
    asm volatile(
        "{\n\t"
        ".reg .pred P1;\n\t"
        "WAIT_LOOP_%=:\n\t"
        "mbarrier.try_wait.parity.shared.b64 P1, [%0], %1, 0x989680;\n\t"
        "@P1 bra.uni WAIT_DONE_%=;\n\t"
        "bra.uni WAIT_LOOP_%=;\n\t"
        "WAIT_DONE_%=:\n\t"
        "}"
        :: "r"(mbar), "r"(parity) : "memory");
}

// -------- init --------
__global__ void init_kernel() {
    int idx = blockIdx.x * blockDim.x + threadIdx.x;
    if (idx < 8) ((unsigned*)g_ctr)[idx] = 0u;
    if (idx < 2 * 2 * H_ * B_) reinterpret_cast<float*>(g_h)[idx] = 0.0f;
}

// -------- precompute: Z0p[t][j][b] = (x @ Wi0^T)[b*T+t][j] + bi0[j] + bs0[j] --------
__global__ void __launch_bounds__(256) precompute_kernel(
    const float* __restrict__ x, const float* __restrict__ Wi,
    const float* __restrict__ bi, const float* __restrict__ bs)
{
    __shared__ float As[16 * AS_STRIDE];
    __shared__ float Bs[16 * AS_STRIDE];
    const int tid = threadIdx.x;
    const int m0 = blockIdx.y * 64;
    const int j0 = blockIdx.x * 64;
    const int lr = tid >> 2;
    const int lq = tid & 3;
    const int tx = tid & 15;
    const int ty = tid >> 4;

    unsigned long long C2[4][2] = {};
    const float* Arow = x  + (size_t)(m0 + lr) * H_ + lq * 4;
    const float* Brow = Wi + (size_t)(j0 + lr) * H_ + lq * 4;

    for (int kc = 0; kc < H_; kc += 16) {
        float4 a4 = *(const float4*)(Arow + kc);
        float4 b4 = *(const float4*)(Brow + kc);
        __syncthreads();
        As[(lq * 4 + 0) * AS_STRIDE + lr] = a4.x;
        As[(lq * 4 + 1) * AS_STRIDE + lr] = a4.y;
        As[(lq * 4 + 2) * AS_STRIDE + lr] = a4.z;
        As[(lq * 4 + 3) * AS_STRIDE + lr] = a4.w;
        Bs[(lq * 4 + 0) * AS_STRIDE + lr] = b4.x;
        Bs[(lq * 4 + 1) * AS_STRIDE + lr] = b4.y;
        Bs[(lq * 4 + 2) * AS_STRIDE + lr] = b4.z;
        Bs[(lq * 4 + 3) * AS_STRIDE + lr] = b4.w;
        __syncthreads();
        #pragma unroll
        for (int k = 0; k < 16; k++) {
            float4 av = *(const float4*)&As[k * AS_STRIDE + ty * 4];
            ulonglong2 bp = *(const ulonglong2*)&Bs[k * AS_STRIDE + tx * 4];
            #pragma unroll
            for (int i = 0; i < 4; i++) {
                float a = (i == 0) ? av.x : (i == 1) ? av.y : (i == 2) ? av.z : av.w;
                unsigned long long a2 = dup2(a);
                fma2(C2[i][0], bp.x, a2);
                fma2(C2[i][1], bp.y, a2);
            }
        }
    }
    #pragma unroll
    for (int i = 0; i < 4; i++) {
        int m = m0 + ty * 4 + i;
        int bb = m >> 10, tt = m & 1023;
        #pragma unroll
        for (int jp = 0; jp < 2; jp++) {
            float lo, hi;
            asm("mov.b64 {%0, %1}, %2;" : "=f"(lo), "=f"(hi) : "l"(C2[i][jp]));
            int jg = j0 + tx * 4 + jp * 2;
            g_Z0p[((size_t)tt * G4 + jg + 0) * B_ + bb] = lo + bi[jg + 0] + bs[jg + 0];
            g_Z0p[((size_t)tt * G4 + jg + 1) * B_ + bb] = hi + bi[jg + 1] + bs[jg + 1];
        }
    }
}

#define FMA4(ACC, BASE, HA, HB, W2V)                      \
    fma2(ACC[(BASE) + 0], HA.x, W2V);                     \
    fma2(ACC[(BASE) + 1], HA.y, W2V);                     \
    fma2(ACC[(BASE) + 2], HB.x, W2V);                     \
    fma2(ACC[(BASE) + 3], HB.y, W2V);

// -------- recurrent persistent kernel: dataflow-synced, no global barrier --------
// Iteration t (0..T_): layer0 computes time t (t<T_); layer1 computes time t-1 (t>=1).
__global__ void __launch_bounds__(THR, 1) recurrent_kernel(
    const float* __restrict__ x, const float* __restrict__ Wi,
    const float* __restrict__ bi, const float* __restrict__ Ws,
    const float* __restrict__ bs, float* __restrict__ out)
{
    extern __shared__ float smem[];
    float* w01  = smem + W01_OFF;
    float* w2   = smem + W2_OFF;
    float* bufA = smem + BUFA_OFF;   // h0 tile -> zI (layer1 z)
    float* bufB = smem + BUFB_OFF;   // h1 tile -> zS (layer0 z)
    unsigned long long* mbars = (unsigned long long*)(smem + MBAR_OFF);
    float* h0r = smem + H0R_OFF;     // [2][128] residual stash

    const int tid = threadIdx.x;
    const int cta = blockIdx.x;
    const unsigned bufAu = smem_u32(bufA);
    const unsigned bufBu = smem_u32(bufB);

    if (tid == 0) {
        #pragma unroll
        for (int c = 0; c < 8; c++) mbar_init(smem_u32(&mbars[c]), 1);
    }

    // ---- load weights into packed SMEM layouts (once) ----
    // slice 0: Ws layer0, slice 1: Wi layer1  -> w01[k][jp][4] = {s0c0,s0c1,s1c0,s1c1}
    // slice 2: Ws layer1                      -> w2 [k][jp][2]
    for (int idx = tid; idx < 3 * 16 * 512; idx += THR) {
        int s  = idx >> 13;
        int r  = idx & 8191;
        int jj = r >> 9;
        int k  = r & 511;
        int g = jj >> 2, cc = jj & 3;
        int grow = g * H_ + cta * 4 + cc;
        const float* src;
        if (s == 0)      src = Ws + (size_t)grow * H_;
        else if (s == 1) src = Wi + (size_t)(G4 + grow) * H_;
        else             src = Ws + (size_t)(G4 + grow) * H_;
        float v = src[k];
        int jp = jj >> 1, lohi = jj & 1;
        if (s < 2) w01[(k * 8 + jp) * 4 + s * 2 + lohi] = v;
        else       w2 [(k * 8 + jp) * 2 + lohi] = v;
    }
    __syncthreads();     // weights + mbarriers visible

    // ---- GEMM thread mapping: bg(4, 8 b each) x jp(8, 2 cols each) x ks(16, 32 k each) ----
    const int bg = tid & 3;
    const int jp = (tid >> 2) & 7;
    const int ks = tid >> 5;          // warp id 0..15
    const int chunk = ks >> 2;        // 16KB chunk this warp reads
    const int bg2 = bg * 2;

    // ---- cell thread mapping (tid < 256) ----
    const bool is_cell = tid < 256;
    const int layer = (tid >> 7) & 1;
    const int ub  = tid & 31;
    const int ucc = (tid >> 5) & 3;
    const int col = cta * 4 + ucc;

    // ---- issue thread mapping (warp 15, tid 480..487) ----
    const bool is_issue = (tid >= 480) && (tid < 488);
    const int ij = tid - 480;                       // 0..7: 0-3 bufA chunks, 4-7 bufB chunks

    float b1g0 = 0.f, b1g1 = 0.f, b1g2 = 0.f, b1g3 = 0.f;
    if (is_cell && layer == 1) {
        b1g0 = bi[G4 + 0 * H_ + col] + bs[G4 + 0 * H_ + col];
        b1g1 = bi[G4 + 1 * H_ + col] + bs[G4 + 1 * H_ + col];
        b1g2 = bi[G4 + 2 * H_ + col] + bs[G4 + 2 * H_ + col];
        b1g3 = bi[G4 + 3 * H_ + col] + bs[G4 + 3 * H_ + col];
    }

    float cst = 0.0f;

    const ulonglong2* h2A = (const ulonglong2*)bufA;
    const ulonglong2* h2B = (const ulonglong2*)bufB;
    const float4* w01p_base = (const float4*)w01 + ks * 32 * 8 + jp;
    const float2* w2p_base  = (const float2*)w2  + ks * 32 * 8 + jp;
    const int zoff = (ks * 16 + jp * 2) * Z_STRIDE + bg * 8;
    float* zS = bufB;   // layer0 z partials live in bufB after GEMM
    float* zI = bufA;   // layer1 z partials live in bufA after GEMM

    for (int t = 0; t <= T_; t++) {
        const int cur = t & 1, prv = cur ^ 1;
        const unsigned parity = (unsigned)(t & 1);

        // ---- issue threads: poll this chunk's producers (acquire), then fire bulk ----
        if (is_issue) {
            const int tile = ij >> 2, ch = ij & 3;
            const unsigned target = 32u * (unsigned)t;
            const unsigned* ctr = &g_ctr[tile][ch];
            while (ld_acq(ctr) < target) { }
            const char* src = (tile == 0) ? (const char*)&g_h[0][prv][0][0]
                                          : (const char*)&g_h[1][cur][0][0];
            unsigned dst = (tile == 0) ? bufAu : bufBu;
            unsigned mb = smem_u32(&mbars[ij]);
            mbar_expect_tx(mb, 16384);
            bulk_g2s(dst + ch * 16384, src + ch * 16384, 16384, mb);
        }

        // ---- global prefetches (independent of staging) ----
        float zp0 = 0.f, zp1 = 0.f, zp2 = 0.f, zp3 = 0.f, xv = 0.f;
        if (is_cell && layer == 0 && t < T_) {
            zp0 = g_Z0p[((size_t)t * G4 + 0 * H_ + col) * B_ + ub];
            zp1 = g_Z0p[((size_t)t * G4 + 1 * H_ + col) * B_ + ub];
            zp2 = g_Z0p[((size_t)t * G4 + 2 * H_ + col) * B_ + ub];
            zp3 = g_Z0p[((size_t)t * G4 + 3 * H_ + col) * B_ + ub];
            xv  = x[((size_t)ub * T_ + t) * H_ + col];
        }

        // ---- wait for this warp's h0 chunk, fused slices 0+1 ----
        mbar_wait(smem_u32(&mbars[chunk]), parity);

        unsigned long long S[8] = {};   // layer0 recurrent: 2 cols x 4 b-pairs
        unsigned long long I[8] = {};   // layer1 input
        {
            const ulonglong2* hp = h2A + ks * 32 * 8 + bg2;
            const float4* wp = w01p_base;
            #pragma unroll 8
            for (int k = 0; k < 32; k++) {
                float4 wv = *wp;
                ulonglong2 hA = hp[0];
                ulonglong2 hB = hp[1];
                unsigned long long t2;
                t2 = dup2(wv.x); FMA4(S, 0, hA, hB, t2);
                t2 = dup2(wv.y); FMA4(S, 4, hA, hB, t2);
                t2 = dup2(wv.z); FMA4(I, 0, hA, hB, t2);
                t2 = dup2(wv.w); FMA4(I, 4, hA, hB, t2);
                wp += 8; hp += 8;
            }
        }

        // ---- wait for this warp's h1 chunk, slice 2 accumulates into I ----
        mbar_wait(smem_u32(&mbars[4 + chunk]), parity);
        {
            const ulonglong2* hp = h2B + ks * 32 * 8 + bg2;
            const float2* wp = w2p_base;
            #pragma unroll 8
            for (int k = 0; k < 32; k++) {
                float2 wv = *wp;
                ulonglong2 hA = hp[0];
                ulonglong2 hB = hp[1];
                unsigned long long t2;
                t2 = dup2(wv.x); FMA4(I, 0, hA, hB, t2);
                t2 = dup2(wv.y); FMA4(I, 4, hA, hB, t2);
                wp += 8; hp += 8;
            }
        }

        __syncthreads();      // all reads of bufA/bufB complete -> safe to overwrite with z

        {
            float* zbS = zS + zoff;
            float* zbI = zI + zoff;
            *(ulonglong2*)(zbS)                  = make_ulonglong2(S[0], S[1]);
            *(ulonglong2*)(zbS + 4)              = make_ulonglong2(S[2], S[3]);
            *(ulonglong2*)(zbS + Z_STRIDE)       = make_ulonglong2(S[4], S[5]);
            *(ulonglong2*)(zbS + Z_STRIDE + 4)   = make_ulonglong2(S[6], S[7]);
            *(ulonglong2*)(zbI)                  = make_ulonglong2(I[0], I[1]);
            *(ulonglong2*)(zbI + 4)              = make_ulonglong2(I[2], I[3]);
            *(ulonglong2*)(zbI + Z_STRIDE)       = make_ulonglong2(I[4], I[5]);
            *(ulonglong2*)(zbI + Z_STRIDE + 4)   = make_ulonglong2(I[6], I[7]);
        }
        __syncthreads();      // z visible

        // ---- layer-0 cells: compute h0(t), publish ctr0 early via partial barrier ----
        if (tid < 128) {
            if (t < T_) {
                float zi = zp0, zf = zp1, zg = zp2, zo = zp3;
                #pragma unroll
                for (int p = 0; p < 16; p++) {
                    const float* zr = zS + p * 16 * Z_STRIDE + ub;
                    zi += zr[(0 * 4 + ucc) * Z_STRIDE];
                    zf += zr[(1 * 4 + ucc) * Z_STRIDE];
                    zg += zr[(2 * 4 + ucc) * Z_STRIDE];
                    zo += zr[(3 * 4 + ucc) * Z_STRIDE];
                }
                cst = fmaf(fsigm(zf), cst, fsigm(zi) * ftanh(zg));
                float hv = fmaf(fsigm(zo), ftanh(cst), xv);
                g_h[0][cur][col][ub] = hv;
                h0r[cur * 128 + ucc * 32 + ub] = hv;
                if (t == T_ - 1) {
                    float* hf = out + (size_t)B_ * T_ * H_;
                    float* cf = hf + (size_t)B_ * 2 * H_;
                    hf[((size_t)ub * 2 + 0) * H_ + col] = hv;
                    cf[((size_t)ub * 2 + 0) * H_ + col] = cst;
                }
            }
            asm volatile("bar.sync 1, 128;" ::: "memory");
            if (tid == 0) {
                __threadfence();
                atomicAdd(&g_ctr[0][cta >> 5], 1u);
            }
        } else if (is_cell) {
            // ---- layer-1 cells (concurrent with layer-0 publication) ----
            if (t >= 1) {
                float zi = b1g0, zf = b1g1, zg = b1g2, zo = b1g3;
                #pragma unroll
                for (int p = 0; p < 16; p++) {
                    const float* zr = zI + p * 16 * Z_STRIDE + ub;
                    zi += zr[(0 * 4 + ucc) * Z_STRIDE];
                    zf += zr[(1 * 4 + ucc) * Z_STRIDE];
                    zg += zr[(2 * 4 + ucc) * Z_STRIDE];
                    zo += zr[(3 * 4 + ucc) * Z_STRIDE];
                }
                cst = fmaf(fsigm(zf), cst, fsigm(zi) * ftanh(zg));
                float hv = fmaf(fsigm(zo), ftanh(cst), h0r[prv * 128 + ucc * 32 + ub]);
                g_h[1][prv][col][ub] = hv;                          // h1(t-1)
                out[((size_t)ub * T_ + (t - 1)) * H_ + col] = hv;
                if (t == T_) {
                    float* hf = out + (size_t)B_ * T_ * H_;
                    float* cf = hf + (size_t)B_ * 2 * H_;
                    hf[((size_t)ub * 2 + 1) * H_ + col] = hv;
                    cf[((size_t)ub * 2 + 1) * H_ + col] = cst;
                }
            }
        }

        __syncthreads();      // cells done: bufs free for next TMA; h1 writes complete
        if (tid == 0) {
            __threadfence();
            atomicAdd(&g_ctr[1][cta >> 5], 1u);
        }
    }
}

extern "C" void kernel_launch(void* const* d_in, const int* in_sizes, int n_in,
                              void* d_out, int out_size)
{
    const float* x  = (const float*)d_in[0];
    const float* Wi = (const float*)d_in[1];
    const float* bi = (const float*)d_in[2];
    const float* Ws = (const float*)d_in[3];
    const float* bs = (const float*)d_in[4];
    float* out = (float*)d_out;

    cudaFuncSetAttribute(recurrent_kernel,
                         cudaFuncAttributeMaxDynamicSharedMemorySize, SMEM_BYTES);

    init_kernel<<<256, 256>>>();
    precompute_kernel<<<dim3(32, 512), 256>>>(x, Wi, bi, bs);
    recurrent_kernel<<<NCTA, THR, SMEM_BYTES>>>(x, Wi, bi, Ws, bs, out);
}

// round 15
// speedup vs baseline: 1.1652x; 1.1652x over previous
#include <cuda_runtime.h>
#include <cuda_bf16.h>
#include <cstddef>
#include <math.h>

// Problem dims
static constexpr int B_  = 32;
static constexpr int T_  = 1024;
static constexpr int H_  = 512;
static constexpr int G4  = 2048;   // 4*H gate columns per layer
static constexpr int NCTA = 128;   // persistent CTAs, each owns 4 hidden cols
static constexpr int THR  = 512;   // threads per recurrent CTA

static constexpr int AS_STRIDE = 68;   // precompute tiles
static constexpr int Z_STRIDE  = 36;   // z rows: 16B-aligned, 36%32=4

// Recurrent SMEM layout (floats):
//   w01 [512][8][4]  (slices 0+1 interleaved)   [0, 16384)
//   w2  [512][8][2]                              [16384, 24576)
//   bufA (h0 tile -> zI)                         [24576, 40960)
//   bufB (h1 tile -> zS)                         [40960, 57344)
//   mbars (8 x 8B)                               [57344, 57360)
//   h0r  [2][128] residual stash                 [57360, 57616)
static constexpr int W01_OFF  = 0;
static constexpr int W2_OFF   = 16384;
static constexpr int BUFA_OFF = 24576;
static constexpr int BUFB_OFF = 40960;
static constexpr int MBAR_OFF = 57344;
static constexpr int H0R_OFF  = 57360;
static constexpr int SMEM_FLOATS = 57616;
static constexpr int SMEM_BYTES  = SMEM_FLOATS * 4;   // 230464

// -------- device-global scratch (allocations forbidden) --------
__device__ __align__(128) float g_Z0p[(size_t)T_ * G4 * B_];   // [t][gate_col][b]
__device__ __align__(128) float g_h[2][2][H_][B_];             // [layer][parity][col][b]
__device__ unsigned g_count;
__device__ volatile unsigned g_release;

__device__ __forceinline__ float fsigm(float z) { return 1.0f / (1.0f + __expf(-z)); }
__device__ __forceinline__ float ftanh(float z) { return 2.0f / (1.0f + __expf(-2.0f * z)) - 1.0f; }

__device__ __forceinline__ unsigned long long dup2(float v) {
    unsigned long long r;
    asm("mov.b64 %0, {%1, %1};" : "=l"(r) : "f"(v));
    return r;
}
__device__ __forceinline__ void fma2(unsigned long long& acc,
                                     unsigned long long a, unsigned long long b) {
    asm("fma.rn.f32x2 %0, %1, %2, %0;" : "+l"(acc) : "l"(a), "l"(b));
}

// -------- mbarrier / bulk-copy helpers --------
__device__ __forceinline__ unsigned smem_u32(const void* p) {
    return (unsigned)__cvta_generic_to_shared(p);
}
__device__ __forceinline__ void mbar_init(unsigned mbar, unsigned cnt) {
    asm volatile("mbarrier.init.shared.b64 [%0], %1;" :: "r"(mbar), "r"(cnt) : "memory");
}
__device__ __forceinline__ void mbar_expect_tx(unsigned mbar, unsigned bytes) {
    asm volatile("mbarrier.arrive.expect_tx.shared.b64 _, [%0], %1;"
                 :: "r"(mbar), "r"(bytes) : "memory");
}
__device__ __forceinline__ void bulk_g2s(unsigned dst, const void* src, unsigned bytes,
                                         unsigned mbar) {
    asm volatile("cp.async.bulk.shared::cta.global.mbarrier::complete_tx::bytes "
                 "[%0], [%1], %2, [%3];"
                 :: "r"(dst), "l"(src), "r"(bytes), "r"(mbar) : "memory");
}
__device__ __forceinline__ void mbar_wait(unsigned mbar, unsigned parity) {
    asm volatile(
        "{\n\t"
        ".reg .pred P1;\n\t"
        "WAIT_LOOP_%=:\n\t"
        "mbarrier.try_wait.parity.shared.b64 P1, [%0], %1, 0x989680;\n\t"
        "@P1 bra.uni WAIT_DONE_%=;\n\t"
        "bra.uni WAIT_LOOP_%=;\n\t"
        "WAIT_DONE_%=:\n\t"
        "}"
        :: "r"(mbar), "r"(parity) : "memory");
}

// -------- init --------
__global__ void init_kernel() {
    int idx = blockIdx.x * blockDim.x + threadIdx.x;
    if (idx == 0) { g_count = 0u; g_release = 0u; }
    if (idx < 2 * 2 * H_ * B_) reinterpret_cast<float*>(g_h)[idx] = 0.0f;
}

// -------- precompute: Z0p[t][j][b] = (x @ Wi0^T)[b*T+t][j] + bi0[j] + bs0[j] --------
__global__ void __launch_bounds__(256) precompute_kernel(
    const float* __restrict__ x, const float* __restrict__ Wi,
    const float* __restrict__ bi, const float* __restrict__ bs)
{
    __shared__ float As[16 * AS_STRIDE];
    __shared__ float Bs[16 * AS_STRIDE];
    const int tid = threadIdx.x;
    const int m0 = blockIdx.y * 64;
    const int j0 = blockIdx.x * 64;
    const int lr = tid >> 2;
    const int lq = tid & 3;
    const int tx = tid & 15;
    const int ty = tid >> 4;

    unsigned long long C2[4][2] = {};
    const float* Arow = x  + (size_t)(m0 + lr) * H_ + lq * 4;
    const float* Brow = Wi + (size_t)(j0 + lr) * H_ + lq * 4;

    for (int kc = 0; kc < H_; kc += 16) {
        float4 a4 = *(const float4*)(Arow + kc);
        float4 b4 = *(const float4*)(Brow + kc);
        __syncthreads();
        As[(lq * 4 + 0) * AS_STRIDE + lr] = a4.x;
        As[(lq * 4 + 1) * AS_STRIDE + lr] = a4.y;
        As[(lq * 4 + 2) * AS_STRIDE + lr] = a4.z;
        As[(lq * 4 + 3) * AS_STRIDE + lr] = a4.w;
        Bs[(lq * 4 + 0) * AS_STRIDE + lr] = b4.x;
        Bs[(lq * 4 + 1) * AS_STRIDE + lr] = b4.y;
        Bs[(lq * 4 + 2) * AS_STRIDE + lr] = b4.z;
        Bs[(lq * 4 + 3) * AS_STRIDE + lr] = b4.w;
        __syncthreads();
        #pragma unroll
        for (int k = 0; k < 16; k++) {
            float4 av = *(const float4*)&As[k * AS_STRIDE + ty * 4];
            ulonglong2 bp = *(const ulonglong2*)&Bs[k * AS_STRIDE + tx * 4];
            #pragma unroll
            for (int i = 0; i < 4; i++) {
                float a = (i == 0) ? av.x : (i == 1) ? av.y : (i == 2) ? av.z : av.w;
                unsigned long long a2 = dup2(a);
                fma2(C2[i][0], bp.x, a2);
                fma2(C2[i][1], bp.y, a2);
            }
        }
    }
    #pragma unroll
    for (int i = 0; i < 4; i++) {
        int m = m0 + ty * 4 + i;
        int bb = m >> 10, tt = m & 1023;
        #pragma unroll
        for (int jp = 0; jp < 2; jp++) {
            float lo, hi;
            asm("mov.b64 {%0, %1}, %2;" : "=f"(lo), "=f"(hi) : "l"(C2[i][jp]));
            int jg = j0 + tx * 4 + jp * 2;
            g_Z0p[((size_t)tt * G4 + jg + 0) * B_ + bb] = lo + bi[jg + 0] + bs[jg + 0];
            g_Z0p[((size_t)tt * G4 + jg + 1) * B_ + bb] = hi + bi[jg + 1] + bs[jg + 1];
        }
    }
}

#define FMA4(ACC, BASE, HA, HB, W2V)                      \
    fma2(ACC[(BASE) + 0], HA.x, W2V);                     \
    fma2(ACC[(BASE) + 1], HA.y, W2V);                     \
    fma2(ACC[(BASE) + 2], HB.x, W2V);                     \
    fma2(ACC[(BASE) + 3], HB.y, W2V);

// -------- recurrent persistent kernel (R12 structure + packed weights + h0r stash) --
// Iteration t (0..T_): layer0 computes time t (t<T_); layer1 computes time t-1 (t>=1).
__global__ void __launch_bounds__(THR, 1) recurrent_kernel(
    const float* __restrict__ x, const float* __restrict__ Wi,
    const float* __restrict__ bi, const float* __restrict__ Ws,
    const float* __restrict__ bs, float* __restrict__ out)
{
    extern __shared__ float smem[];
    float* w01  = smem + W01_OFF;
    float* w2   = smem + W2_OFF;
    float* bufA = smem + BUFA_OFF;   // h0 tile -> zI (layer1 z)
    float* bufB = smem + BUFB_OFF;   // h1 tile -> zS (layer0 z)
    unsigned long long* mbars = (unsigned long long*)(smem + MBAR_OFF);
    float* h0r = smem + H0R_OFF;     // [2][128] residual stash

    const int tid = threadIdx.x;
    const int cta = blockIdx.x;
    const unsigned mbarA0 = smem_u32(&mbars[0]);
    const unsigned mbarB0 = smem_u32(&mbars[4]);
    const unsigned bufAu = smem_u32(bufA);
    const unsigned bufBu = smem_u32(bufB);

    if (tid == 0) {
        #pragma unroll
        for (int c = 0; c < 8; c++) mbar_init(smem_u32(&mbars[c]), 1);
    }

    // ---- load weights into packed SMEM layouts (once) ----
    // slice 0: Ws layer0, slice 1: Wi layer1  -> w01[k][jp][4] = {s0c0,s0c1,s1c0,s1c1}
    // slice 2: Ws layer1                      -> w2 [k][jp][2]
    for (int idx = tid; idx < 3 * 16 * 512; idx += THR) {
        int s  = idx >> 13;
        int r  = idx & 8191;
        int jj = r >> 9;
        int k  = r & 511;
        int g = jj >> 2, cc = jj & 3;
        int grow = g * H_ + cta * 4 + cc;
        const float* src;
        if (s == 0)      src = Ws + (size_t)grow * H_;
        else if (s == 1) src = Wi + (size_t)(G4 + grow) * H_;
        else             src = Ws + (size_t)(G4 + grow) * H_;
        float v = src[k];
        int jp = jj >> 1, lohi = jj & 1;
        if (s < 2) w01[(k * 8 + jp) * 4 + s * 2 + lohi] = v;
        else       w2 [(k * 8 + jp) * 2 + lohi] = v;
    }
    __syncthreads();     // weights + mbarriers visible

    // ---- GEMM thread mapping: bg(4, 8 b each) x jp(8, 2 cols each) x ks(16, 32 k each) ----
    const int bg = tid & 3;
    const int jp = (tid >> 2) & 7;
    const int ks = tid >> 5;          // warp id 0..15
    const int chunk = ks >> 2;        // 16KB chunk this warp reads
    const int bg2 = bg * 2;

    // ---- cell thread mapping (tid < 256) ----
    const bool is_cell = tid < 256;
    const int layer = (tid >> 7) & 1;
    const int ub  = tid & 31;
    const int ucc = (tid >> 5) & 3;
    const int col = cta * 4 + ucc;

    float b1g0 = 0.f, b1g1 = 0.f, b1g2 = 0.f, b1g3 = 0.f;
    if (is_cell && layer == 1) {
        b1g0 = bi[G4 + 0 * H_ + col] + bs[G4 + 0 * H_ + col];
        b1g1 = bi[G4 + 1 * H_ + col] + bs[G4 + 1 * H_ + col];
        b1g2 = bi[G4 + 2 * H_ + col] + bs[G4 + 2 * H_ + col];
        b1g3 = bi[G4 + 3 * H_ + col] + bs[G4 + 3 * H_ + col];
    }

    float cst = 0.0f;
    unsigned epoch = 0;

    const ulonglong2* h2A = (const ulonglong2*)bufA;
    const ulonglong2* h2B = (const ulonglong2*)bufB;
    const float4* w01p_base = (const float4*)w01 + ks * 32 * 8 + jp;
    const float2* w2p_base  = (const float2*)w2  + ks * 32 * 8 + jp;
    const int zoff = (ks * 16 + jp * 2) * Z_STRIDE + bg * 8;
    float* zS = bufB;   // layer0 z partials live in bufB after GEMM
    float* zI = bufA;   // layer1 z partials live in bufA after GEMM

    for (int t = 0; t <= T_; t++) {
        const int cur = t & 1, prv = cur ^ 1;
        const unsigned parity = (unsigned)(t & 1);

        // ---- issue both h tile bulk loads, 4 chunks each (tid 0) ----
        if (tid == 0) {
            const char* srcA = (const char*)&g_h[0][prv][0][0];  // h0(t-1)
            const char* srcB = (const char*)&g_h[1][cur][0][0];  // h1(t-2)
            #pragma unroll
            for (int c = 0; c < 4; c++) {
                mbar_expect_tx(mbarA0 + c * 8, 16384);
                bulk_g2s(bufAu + c * 16384, srcA + c * 16384, 16384, mbarA0 + c * 8);
            }
            #pragma unroll
            for (int c = 0; c < 4; c++) {
                mbar_expect_tx(mbarB0 + c * 8, 16384);
                bulk_g2s(bufBu + c * 16384, srcB + c * 16384, 16384, mbarB0 + c * 8);
            }
        }

        // ---- global prefetches (independent of staging) ----
        float zp0 = 0.f, zp1 = 0.f, zp2 = 0.f, zp3 = 0.f, xv = 0.f;
        if (is_cell && layer == 0 && t < T_) {
            zp0 = g_Z0p[((size_t)t * G4 + 0 * H_ + col) * B_ + ub];
            zp1 = g_Z0p[((size_t)t * G4 + 1 * H_ + col) * B_ + ub];
            zp2 = g_Z0p[((size_t)t * G4 + 2 * H_ + col) * B_ + ub];
            zp3 = g_Z0p[((size_t)t * G4 + 3 * H_ + col) * B_ + ub];
            xv  = x[((size_t)ub * T_ + t) * H_ + col];
        }

        // ---- wait for this warp's h0 chunk, fused slices 0+1 (packed w01) ----
        mbar_wait(mbarA0 + chunk * 8, parity);

        unsigned long long S[8] = {};   // layer0 recurrent: 2 cols x 4 b-pairs
        unsigned long long I[8] = {};   // layer1 input
        {
            const ulonglong2* hp = h2A + ks * 32 * 8 + bg2;
            const float4* wp = w01p_base;
            #pragma unroll 8
            for (int k = 0; k < 32; k++) {
                float4 wv = *wp;
                ulonglong2 hA = hp[0];
                ulonglong2 hB = hp[1];
                unsigned long long t2;
                t2 = dup2(wv.x); FMA4(S, 0, hA, hB, t2);
                t2 = dup2(wv.y); FMA4(S, 4, hA, hB, t2);
                t2 = dup2(wv.z); FMA4(I, 0, hA, hB, t2);
                t2 = dup2(wv.w); FMA4(I, 4, hA, hB, t2);
                wp += 8; hp += 8;
            }
        }

        // ---- wait for this warp's h1 chunk, slice 2 accumulates into I ----
        mbar_wait(mbarB0 + chunk * 8, parity);
        {
            const ulonglong2* hp = h2B + ks * 32 * 8 + bg2;
            const float2* wp = w2p_base;
            #pragma unroll 8
            for (int k = 0; k < 32; k++) {
                float2 wv = *wp;
                ulonglong2 hA = hp[0];
                ulonglong2 hB = hp[1];
                unsigned long long t2;
                t2 = dup2(wv.x); FMA4(I, 0, hA, hB, t2);
                t2 = dup2(wv.y); FMA4(I, 4, hA, hB, t2);
                wp += 8; hp += 8;
            }
        }

        __syncthreads();      // all reads of bufA/bufB complete -> safe to overwrite with z

        {
            float* zbS = zS + zoff;
            float* zbI = zI + zoff;
            *(ulonglong2*)(zbS)                  = make_ulonglong2(S[0], S[1]);
            *(ulonglong2*)(zbS + 4)              = make_ulonglong2(S[2], S[3]);
            *(ulonglong2*)(zbS + Z_STRIDE)       = make_ulonglong2(S[4], S[5]);
            *(ulonglong2*)(zbS + Z_STRIDE + 4)   = make_ulonglong2(S[6], S[7]);
            *(ulonglong2*)(zbI)                  = make_ulonglong2(I[0], I[1]);
            *(ulonglong2*)(zbI + 4)              = make_ulonglong2(I[2], I[3]);
            *(ulonglong2*)(zbI + Z_STRIDE)       = make_ulonglong2(I[4], I[5]);
            *(ulonglong2*)(zbI + Z_STRIDE + 4)   = make_ulonglong2(I[6], I[7]);
        }
        __syncthreads();      // z visible

        // ---- both cell updates run concurrently (256 threads) ----
        if (is_cell) {
            if (layer == 0) {
                if (t < T_) {
                    float zi = zp0, zf = zp1, zg = zp2, zo = zp3;
                    #pragma unroll
                    for (int p = 0; p < 16; p++) {
                        const float* zr = zS + p * 16 * Z_STRIDE + ub;
                        zi += zr[(0 * 4 + ucc) * Z_STRIDE];
                        zf += zr[(1 * 4 + ucc) * Z_STRIDE];
                        zg += zr[(2 * 4 + ucc) * Z_STRIDE];
                        zo += zr[(3 * 4 + ucc) * Z_STRIDE];
                    }
                    cst = fmaf(fsigm(zf), cst, fsigm(zi) * ftanh(zg));
                    float hv = fmaf(fsigm(zo), ftanh(cst), xv);
                    g_h[0][cur][col][ub] = hv;
                    h0r[cur * 128 + ucc * 32 + ub] = hv;
                    if (t == T_ - 1) {
                        float* hf = out + (size_t)B_ * T_ * H_;
                        float* cf = hf + (size_t)B_ * 2 * H_;
                        hf[((size_t)ub * 2 + 0) * H_ + col] = hv;
                        cf[((size_t)ub * 2 + 0) * H_ + col] = cst;
                    }
                }
            } else {
                if (t >= 1) {
                    float zi = b1g0, zf = b1g1, zg = b1g2, zo = b1g3;
                    #pragma unroll
                    for (int p = 0; p < 16; p++) {
                        const float* zr = zI + p * 16 * Z_STRIDE + ub;
                        zi += zr[(0 * 4 + ucc) * Z_STRIDE];
                        zf += zr[(1 * 4 + ucc) * Z_STRIDE];
                        zg += zr[(2 * 4 + ucc) * Z_STRIDE];
                        zo += zr[(3 * 4 + ucc) * Z_STRIDE];
                    }
                    cst = fmaf(fsigm(zf), cst, fsigm(zi) * ftanh(zg));
                    float hv = fmaf(fsigm(zo), ftanh(cst), h0r[prv * 128 + ucc * 32 + ub]);
                    g_h[1][prv][col][ub] = hv;                          // h1(t-1)
                    out[((size_t)ub * T_ + (t - 1)) * H_ + col] = hv;
                    if (t == T_) {
                        float* hf = out + (size_t)B_ * T_ * H_;
                        float* cf = hf + (size_t)B_ * 2 * H_;
                        hf[((size_t)ub * 2 + 1) * H_ + col] = hv;
                        cf[((size_t)ub * 2 + 1) * H_ + col] = cst;
                    }
                }
            }
        }

        // ---- grid barrier (single per step; skipped on last iteration) ----
        if (t < T_) {
            __syncthreads();
            if (tid == 0) {
                ++epoch;
                __threadfence();
                unsigned old = atomicAdd(&g_count, 1u);
                if (old == epoch * NCTA - 1u) {
                    g_release = epoch;
                } else {
                    while (g_release < epoch) { }
                }
                __threadfence();
            }
            __syncthreads();
        }
    }
}

extern "C" void kernel_launch(void* const* d_in, const int* in_sizes, int n_in,
                              void* d_out, int out_size)
{
    const float* x  = (const float*)d_in[0];
    const float* Wi = (const float*)d_in[1];
    const float* bi = (const float*)d_in[2];
    const float* Ws = (const float*)d_in[3];
    const float* bs = (const float*)d_in[4];
    float* out = (float*)d_out;

    cudaFuncSetAttribute(recurrent_kernel,
                         cudaFuncAttributeMaxDynamicSharedMemorySize, SMEM_BYTES);

    init_kernel<<<256, 256>>>();
    precompute_kernel<<<dim3(32, 512), 256>>>(x, Wi, bi, bs);
    recurrent_kernel<<<NCTA, THR, SMEM_BYTES>>>(x, Wi, bi, Ws, bs, out);
}